// round 15
// baseline (speedup 1.0000x reference)
#include <cuda_runtime.h>
#include <cooperative_groups.h>
#include <math_constants.h>

namespace cg = cooperative_groups;

#define NCH   64
#define NPIX  16384      // 128*128
#define BINS  256
#define CSEG  4          // CTAs per channel = cluster size
#define GRID  (NCH * CSEG)      // 256 CTAs
#define SLICE (NPIX / CSEG)     // 4096 elements per CTA
#define VPT   (SLICE / (256 * 4))   // float4s per thread = 4

__device__ float    g_r0[BINS];     // channel-0 correction row
__device__ float    g_scale;        // msum * NCH / size^2
__device__ unsigned g_flag   = 0;   // r0 published
__device__ unsigned g_ticket = 0;

__device__ __forceinline__ float warpSum(float v){
    #pragma unroll
    for (int o = 16; o; o >>= 1) v += __shfl_down_sync(0xffffffffu, v, o);
    return v;
}
__device__ __forceinline__ float warpMin(float v){
    #pragma unroll
    for (int o = 16; o; o >>= 1) v = fminf(v, __shfl_down_sync(0xffffffffu, v, o));
    return v;
}
__device__ __forceinline__ float warpMax(float v){
    #pragma unroll
    for (int o = 16; o; o >>= 1) v = fmaxf(v, __shfl_down_sync(0xffffffffu, v, o));
    return v;
}

__global__ void __cluster_dims__(CSEG, 1, 1) __launch_bounds__(256) k_all(
    const float* __restrict__ input,
    const float* __restrict__ match,
    const float* __restrict__ mask,
    float* __restrict__ out)
{
    cg::cluster_group cluster = cg::this_cluster();
    const int c    = blockIdx.x / CSEG;               // channel
    const int seg  = (int)cluster.block_rank();       // 0..3
    const int t    = threadIdx.x;
    const int lane = t & 31, w = t >> 5;
    const int base = seg * SLICE;

    __shared__ float sred[8][5];
    __shared__ float s_stat[8];   // [0]mnM [1]mxM [2]mnX0 [3]mxX0 [4]msum [5]mn [6]safe_w
    __shared__ int   s_hist[BINS];
    __shared__ float s_cdf[BINS];
    __shared__ float s_sc[8];
    __shared__ float r0s[BINS];

    s_hist[t] = 0;

    // ───── Phase A: ONE global pass. Keep match*mask AND input*mask in registers ─────
    float4 pm[VPT];   // match * mask  (for histogram)
    float4 xm[VPT];   // input * mask  (for loss)
    {
        const float4* __restrict__ m4 = (const float4*)(match + c * NPIX + base);
        const float4* __restrict__ k4 = (const float4*)(mask + base);
        const float4* __restrict__ x4 = (const float4*)(input + c * NPIX + base);

        float mnM =  CUDART_INF_F, mxM = -CUDART_INF_F;
        float mnX =  CUDART_INF_F, mxX = -CUDART_INF_F;
        float ms  = 0.f;

        #pragma unroll
        for (int k = 0; k < VPT; k++) {
            const int i = t + 256 * k;
            float4 a = m4[i], bb = k4[i], xv = x4[i];
            float4 p, q;
            p.x = a.x * bb.x;  p.y = a.y * bb.y;  p.z = a.z * bb.z;  p.w = a.w * bb.w;
            q.x = xv.x * bb.x; q.y = xv.y * bb.y; q.z = xv.z * bb.z; q.w = xv.w * bb.w;
            pm[k] = p;  xm[k] = q;
            mnM = fminf(fminf(mnM, p.x), fminf(p.y, fminf(p.z, p.w)));
            mxM = fmaxf(fmaxf(mxM, p.x), fmaxf(p.y, fmaxf(p.z, p.w)));
            if (c == 0) {
                mnX = fminf(fminf(mnX, q.x), fminf(q.y, fminf(q.z, q.w)));
                mxX = fmaxf(fmaxf(mxX, q.x), fmaxf(q.y, fmaxf(q.z, q.w)));
                ms += (bb.x + bb.y) + (bb.z + bb.w);
            }
        }

        mnM = warpMin(mnM);  mxM = warpMax(mxM);
        mnX = warpMin(mnX);  mxX = warpMax(mxX);
        ms  = warpSum(ms);
        if (lane == 0) {
            sred[w][0] = mnM; sred[w][1] = mxM;
            sred[w][2] = mnX; sred[w][3] = mxX;
            sred[w][4] = ms;
        }
        __syncthreads();
        if (t == 0) {
            float a = sred[0][0], bb = sred[0][1];
            float d = sred[0][2], e = sred[0][3];
            float f = sred[0][4];
            #pragma unroll
            for (int i = 1; i < 8; i++) {
                a = fminf(a, sred[i][0]); bb = fmaxf(bb, sred[i][1]);
                d = fminf(d, sred[i][2]); e  = fmaxf(e,  sred[i][3]);
                f += sred[i][4];
            }
            s_stat[0] = a;  s_stat[1] = bb;
            s_stat[2] = d;  s_stat[3] = e;  s_stat[4] = f;
        }
    }

    cluster.sync();

    // Merge channel match-min/max across the 4 CTAs via DSMEM
    if (t == 0) {
        float a =  CUDART_INF_F, bb = -CUDART_INF_F;
        #pragma unroll
        for (int r = 0; r < CSEG; r++) {
            const float* p = cluster.map_shared_rank((const float*)s_stat, r);
            a  = fminf(a,  p[0]);
            bb = fmaxf(bb, p[1]);
        }
        float wM = (bb - a) / (float)BINS;
        s_stat[5] = a;
        s_stat[6] = (wM > 0.f) ? wM : 1.0f;   // torch.histc safe width
    }
    __syncthreads();

    // ───── Phase B: histogram from registers ─────
    {
        const float mn = s_stat[5], wS = s_stat[6];
        #pragma unroll
        for (int k = 0; k < VPT; k++) {
            float p[4] = {pm[k].x, pm[k].y, pm[k].z, pm[k].w};
            #pragma unroll
            for (int j = 0; j < 4; j++) {
                int bi = (int)floorf((p[j] - mn) / wS);
                bi = min(BINS - 1, max(0, bi));
                atomicAdd(&s_hist[bi], 1);
            }
        }
    }
    __syncthreads();
    cluster.sync();

    // ───── Phase C: every CTA merges the 4 hists (DSMEM) and scans locally ─────
    {
        int sum = s_hist[t];
        #pragma unroll
        for (int r = 0; r < CSEG; r++) {
            if (r != seg) {
                const int* ph = cluster.map_shared_rank((const int*)s_hist, r);
                sum += ph[t];
            }
        }
        // warp-shuffle inclusive scan of 256 exact-int counts
        float v = (float)sum;
        #pragma unroll
        for (int o = 1; o < 32; o <<= 1) {
            float n = __shfl_up_sync(0xffffffffu, v, o);
            if (lane >= o) v += n;
        }
        if (lane == 31) s_sc[w] = v;
        __syncthreads();
        if (w == 0) {
            float x = (lane < 8) ? s_sc[lane] : 0.f;
            #pragma unroll
            for (int o = 1; o < 8; o <<= 1) {
                float n = __shfl_up_sync(0xffffffffu, x, o);
                if (lane >= o) x += n;
            }
            if (lane < 8) s_sc[lane] = x;
        }
        __syncthreads();
        if (w > 0) v += s_sc[w - 1];
        s_cdf[t] = v;
        __syncthreads();
    }

    // Cluster 0 rank 0: finish ch-0 stats, build r0, publish, zero out, raise flag
    if (c == 0 && seg == 0) {
        if (t == 0) {
            float d = s_stat[2], e = s_stat[3], f = s_stat[4];
            #pragma unroll
            for (int r = 1; r < CSEG; r++) {
                const float* p = cluster.map_shared_rank((const float*)s_stat, r);
                d = fminf(d, p[2]);
                e = fmaxf(e, p[3]);
                f += p[4];
            }
            s_stat[2] = d;                       // min0
            s_stat[3] = (e - d) / (float)BINS;   // step0
            const float size = (float)(NCH * NPIX);
            g_scale = f * (float)NCH / (size * size);
            __stcg(out, 0.f);
        }
        __syncthreads();

        // r0[j] from CHANNEL-0 quantities (faithful flattened-gather semantics)
        const float rank = (float)(t + 1);
        int lo = 0, hi = BINS;
        #pragma unroll
        for (int it = 0; it < 8; it++) {
            int mid = (lo + hi) >> 1;
            if (s_cdf[mid] < rank) lo = mid + 1; else hi = mid;
        }
        const float prev = lo ? s_cdf[lo - 1] : 0.f;
        float ratio = (rank - prev) / (1e-8f + s_cdf[lo]);
        ratio = fminf(1.f, fmaxf(0.f, ratio));
        __stcg(&g_r0[t], s_stat[2] + (ratio + (float)lo) * s_stat[3]);

        __threadfence();
        __syncthreads();
        if (t == 0) atomicExch(&g_flag, 1u);
    }

    // Cluster-local guard: peers' DSMEM reads (hists, s_stat) complete before
    // anyone races ahead; for cluster 0 it also orders peers behind the publish.
    cluster.sync();

    // Wait for r0 (all 256 CTAs are co-resident; cluster 0 never waits -> no deadlock)
    if (t == 0) {
        while (atomicAdd(&g_flag, 0u) == 0u) __nanosleep(32);
    }
    __syncthreads();
    __threadfence();
    r0s[t] = __ldcg(&g_r0[t]);
    __syncthreads();

    // ───── Phase D: loss from register-held input products ─────
    float acc = 0.f;
    #pragma unroll
    for (int k = 0; k < VPT; k++) {
        const int i  = t + 256 * k;
        const int n0 = base + i * 4;
        float xs[4] = {xm[k].x, xm[k].y, xm[k].z, xm[k].w};

        int lo = 0, hi = BINS;
        const float rank0 = (float)(n0 + 1);
        #pragma unroll
        for (int it = 0; it < 8; it++) {
            int mid = (lo + hi) >> 1;
            if (s_cdf[mid] < rank0) lo = mid + 1; else hi = mid;
        }
        #pragma unroll
        for (int j = 0; j < 4; j++) {
            const float rank = (float)(n0 + j + 1);
            while (lo < BINS - 1 && s_cdf[lo] < rank) lo++;
            const float d = r0s[lo] - xs[j];
            acc += d * d;
        }
    }

    acc = warpSum(acc);
    if (lane == 0) sred[w][0] = acc;
    __syncthreads();
    if (t == 0) {
        float s = 0.f;
        #pragma unroll
        for (int i = 0; i < 8; i++) s += sred[i][0];
        atomicAdd(out, s * __ldcg(&g_scale));   // * WEIGHT (=1.0)

        // Ticket: last block resets flag/ticket for the next graph replay
        unsigned k = atomicAdd(&g_ticket, 1u);
        if (k == GRID - 1) {
            atomicExch(&g_ticket, 0u);
            atomicExch(&g_flag, 0u);
        }
    }
}

extern "C" void kernel_launch(void* const* d_in, const int* in_sizes, int n_in,
                              void* d_out, int out_size)
{
    const float* input = (const float*)d_in[0];
    const float* match = (const float*)d_in[1];
    const float* mask  = (const float*)d_in[2];

    k_all<<<GRID, 256>>>(input, match, mask, (float*)d_out);
}

// round 17
// speedup vs baseline: 1.0173x; 1.0173x over previous
#include <cuda_runtime.h>
#include <math_constants.h>

#define NCH   64
#define NPIX  16384      // 128*128
#define BINS  256
#define MSEG  8          // blocks per channel in k_mm / k_hist
#define LSEG  16         // blocks per channel in k_loss
#define SLICE_M (NPIX / MSEG)   // 2048
#define SLICE_L (NPIX / LSEG)   // 1024
#define GRID_M  (NCH * MSEG)    // 512
#define GRID_L  (NCH * LSEG)    // 1024
#define VPT_M   (SLICE_M / (256 * 4))   // 2 float4s per thread

// Cross-kernel scratch. Everything consumed is re-written every replay:
// g_hist zeroed by k_mm, re-filled by k_hist; partials overwritten by k_mm.
__device__ float g_mm[NCH][MSEG][2];    // match*mask {min,max} partials
__device__ float g_x0mn[MSEG], g_x0mx[MSEG], g_msum[MSEG];
__device__ int   g_hist[NCH][BINS];     // merged per-channel histogram
__device__ float g_min0, g_step0, g_scale;

__device__ __forceinline__ float warpSum(float v){
    #pragma unroll
    for (int o = 16; o; o >>= 1) v += __shfl_down_sync(0xffffffffu, v, o);
    return v;
}
__device__ __forceinline__ float warpMin(float v){
    #pragma unroll
    for (int o = 16; o; o >>= 1) v = fminf(v, __shfl_down_sync(0xffffffffu, v, o));
    return v;
}
__device__ __forceinline__ float warpMax(float v){
    #pragma unroll
    for (int o = 16; o; o >>= 1) v = fmaxf(v, __shfl_down_sync(0xffffffffu, v, o));
    return v;
}

// ───────── K1: streaming min/max partials; zero g_hist and out ─────────
__global__ void __launch_bounds__(256) k_mm(
    const float* __restrict__ input,
    const float* __restrict__ match,
    const float* __restrict__ mask,
    float* __restrict__ out)
{
    cudaTriggerProgrammaticLaunchCompletion();   // let k_hist start prefetching

    const int b   = blockIdx.x;
    const int c   = b / MSEG;
    const int seg = b % MSEG;
    const int t   = threadIdx.x;
    const int lane = t & 31, w = t >> 5;
    const int base = seg * SLICE_M;

    // Zero the merged histogram slice this block owns (ordered before k_hist's
    // atomics by the PDL grid dependency).
    if (t < BINS / MSEG) g_hist[c][seg * (BINS / MSEG) + t] = 0;
    if (b == 0 && t == 0) out[0] = 0.f;

    const float4* __restrict__ m4 = (const float4*)(match + c * NPIX + base);
    const float4* __restrict__ k4 = (const float4*)(mask + base);
    const float4* __restrict__ x4 = (const float4*)(input + base);   // channel 0

    float mnM =  CUDART_INF_F, mxM = -CUDART_INF_F;
    float mnX =  CUDART_INF_F, mxX = -CUDART_INF_F;
    float ms  = 0.f;

    #pragma unroll
    for (int k = 0; k < VPT_M; k++) {
        const int i = t + 256 * k;
        float4 a = m4[i], bb = k4[i];
        float p0 = a.x * bb.x, p1 = a.y * bb.y, p2 = a.z * bb.z, p3 = a.w * bb.w;
        mnM = fminf(fminf(mnM, p0), fminf(p1, fminf(p2, p3)));
        mxM = fmaxf(fmaxf(mxM, p0), fmaxf(p1, fmaxf(p2, p3)));
        if (c == 0) {
            float4 xv = x4[i];
            float q0 = xv.x * bb.x, q1 = xv.y * bb.y, q2 = xv.z * bb.z, q3 = xv.w * bb.w;
            mnX = fminf(fminf(mnX, q0), fminf(q1, fminf(q2, q3)));
            mxX = fmaxf(fmaxf(mxX, q0), fmaxf(q1, fmaxf(q2, q3)));
            ms += (bb.x + bb.y) + (bb.z + bb.w);
        }
    }

    __shared__ float sred[8][5];
    mnM = warpMin(mnM);  mxM = warpMax(mxM);
    mnX = warpMin(mnX);  mxX = warpMax(mxX);
    ms  = warpSum(ms);
    if (lane == 0) {
        sred[w][0] = mnM; sred[w][1] = mxM;
        sred[w][2] = mnX; sred[w][3] = mxX;
        sred[w][4] = ms;
    }
    __syncthreads();
    if (t == 0) {
        float a = sred[0][0], bb = sred[0][1];
        float d = sred[0][2], e = sred[0][3];
        float f = sred[0][4];
        #pragma unroll
        for (int i = 1; i < 8; i++) {
            a = fminf(a, sred[i][0]); bb = fmaxf(bb, sred[i][1]);
            d = fminf(d, sred[i][2]); e  = fmaxf(e,  sred[i][3]);
            f += sred[i][4];
        }
        g_mm[c][seg][0] = a;
        g_mm[c][seg][1] = bb;
        if (c == 0) { g_x0mn[seg] = d; g_x0mx[seg] = e; g_msum[seg] = f; }
    }
}

// ───────── K2 (PDL on K1): prefetch products, sync, histogram ─────────
__global__ void __launch_bounds__(256) k_hist(
    const float* __restrict__ match,
    const float* __restrict__ mask)
{
    const int b   = blockIdx.x;
    const int c   = b / MSEG;
    const int seg = b % MSEG;
    const int t   = threadIdx.x;
    const int base = seg * SLICE_M;

    // Prefetch: compute match*mask products into registers while k_mm runs.
    float p[VPT_M * 4];
    {
        const float4* __restrict__ m4 = (const float4*)(match + c * NPIX + base);
        const float4* __restrict__ k4 = (const float4*)(mask + base);
        #pragma unroll
        for (int k = 0; k < VPT_M; k++) {
            float4 a = m4[t + 256 * k], bb = k4[t + 256 * k];
            p[k*4+0] = a.x * bb.x;  p[k*4+1] = a.y * bb.y;
            p[k*4+2] = a.z * bb.z;  p[k*4+3] = a.w * bb.w;
        }
    }

    cudaTriggerProgrammaticLaunchCompletion();   // let k_loss start prefetching
    cudaGridDependencySynchronize();             // wait for k_mm (partials + zeroed hist)

    __shared__ int   s_hist[BINS];
    __shared__ float sbc[2];                     // mn, safe width
    s_hist[t] = 0;
    if (t == 0) {
        float a = __ldcg(&g_mm[c][0][0]), bb = __ldcg(&g_mm[c][0][1]);
        #pragma unroll
        for (int i = 1; i < MSEG; i++) {
            a  = fminf(a,  __ldcg(&g_mm[c][i][0]));
            bb = fmaxf(bb, __ldcg(&g_mm[c][i][1]));
        }
        float wM = (bb - a) / (float)BINS;
        sbc[0] = a;
        sbc[1] = (wM > 0.f) ? wM : 1.0f;         // torch.histc safe width

        // Block 0 publishes ch-0 input stats + global scale
        if (b == 0) {
            float d = __ldcg(&g_x0mn[0]), e = __ldcg(&g_x0mx[0]), f = __ldcg(&g_msum[0]);
            #pragma unroll
            for (int i = 1; i < MSEG; i++) {
                d = fminf(d, __ldcg(&g_x0mn[i]));
                e = fmaxf(e, __ldcg(&g_x0mx[i]));
                f += __ldcg(&g_msum[i]);
            }
            g_min0  = d;
            g_step0 = (e - d) / (float)BINS;
            const float size = (float)(NCH * NPIX);
            g_scale = f * (float)NCH / (size * size);
        }
    }
    __syncthreads();

    const float mn = sbc[0], wS = sbc[1];
    #pragma unroll
    for (int j = 0; j < VPT_M * 4; j++) {
        int bi = (int)floorf((p[j] - mn) / wS);
        bi = min(BINS - 1, max(0, bi));
        atomicAdd(&s_hist[bi], 1);
    }
    __syncthreads();

    // Merge into the channel histogram: spread addresses, 8-way contention max.
    if (s_hist[t]) atomicAdd(&g_hist[c][t], s_hist[t]);
}

// ───────── K3 (PDL on K2): prefetch input, sync, scan + r0 + loss ─────────
__global__ void __launch_bounds__(256) k_loss(
    const float* __restrict__ input,
    const float* __restrict__ mask,
    float* __restrict__ out)
{
    const int b   = blockIdx.x;
    const int c   = b / LSEG;
    const int seg = b % LSEG;
    const int t   = threadIdx.x;
    const int lane = t & 31, w = t >> 5;
    const int base = seg * SLICE_L;

    // Prefetch this block's data while k_hist (and possibly k_mm) still run.
    const float4* __restrict__ x4 = (const float4*)(input + c * NPIX + base);
    const float4* __restrict__ k4 = (const float4*)(mask + base);
    float4 xv = x4[t];
    float4 mk = k4[t];

    cudaGridDependencySynchronize();             // wait for k_hist (hist + stats)

    __shared__ float cdf0[BINS], cdfc[BINS], r0s[BINS];
    __shared__ float s0[8], sc[8];
    __shared__ float sw_[8];

    float v0 = (float)__ldcg(&g_hist[0][t]);
    float vc = (float)__ldcg(&g_hist[c][t]);

    // Dual warp-shuffle inclusive scan (exact integer counts in fp32)
    #pragma unroll
    for (int o = 1; o < 32; o <<= 1) {
        float n0 = __shfl_up_sync(0xffffffffu, v0, o);
        float nc = __shfl_up_sync(0xffffffffu, vc, o);
        if (lane >= o) { v0 += n0; vc += nc; }
    }
    if (lane == 31) { s0[w] = v0; sc[w] = vc; }
    __syncthreads();
    if (w == 0) {
        float x0 = (lane < 8) ? s0[lane] : 0.f;
        float xc = (lane < 8) ? sc[lane] : 0.f;
        #pragma unroll
        for (int o = 1; o < 8; o <<= 1) {
            float n0 = __shfl_up_sync(0xffffffffu, x0, o);
            float nc = __shfl_up_sync(0xffffffffu, xc, o);
            if (lane >= o) { x0 += n0; xc += nc; }
        }
        if (lane < 8) { s0[lane] = x0; sc[lane] = xc; }
    }
    __syncthreads();
    if (w > 0) { v0 += s0[w - 1]; vc += sc[w - 1]; }
    cdf0[t] = v0;
    cdfc[t] = vc;
    __syncthreads();

    // r0[j] from CHANNEL-0 quantities (faithful flattened-gather semantics)
    {
        const float rank = (float)(t + 1);
        int lo = 0, hi = BINS;
        #pragma unroll
        for (int it = 0; it < 8; it++) {
            int mid = (lo + hi) >> 1;
            if (cdf0[mid] < rank) lo = mid + 1; else hi = mid;
        }
        const float prev = lo ? cdf0[lo - 1] : 0.f;
        float ratio = (rank - prev) / (1e-8f + cdf0[lo]);
        ratio = fminf(1.f, fmaxf(0.f, ratio));
        r0s[t] = __ldcg(&g_min0) + (ratio + (float)lo) * __ldcg(&g_step0);
    }
    __syncthreads();

    // Loss over this block's 1024-element slice: one float4 per thread
    float acc;
    {
        const int n0 = base + t * 4;
        float xs[4] = {xv.x * mk.x, xv.y * mk.y, xv.z * mk.z, xv.w * mk.w};

        int lo = 0, hi = BINS;
        const float rank0 = (float)(n0 + 1);
        #pragma unroll
        for (int it = 0; it < 8; it++) {
            int mid = (lo + hi) >> 1;
            if (cdfc[mid] < rank0) lo = mid + 1; else hi = mid;
        }
        acc = 0.f;
        #pragma unroll
        for (int j = 0; j < 4; j++) {
            const float rank = (float)(n0 + j + 1);
            while (lo < BINS - 1 && cdfc[lo] < rank) lo++;
            const float d = r0s[lo] - xs[j];
            acc += d * d;
        }
    }

    acc = warpSum(acc);
    if (lane == 0) sw_[w] = acc;
    __syncthreads();
    if (t == 0) {
        float s = 0.f;
        #pragma unroll
        for (int i = 0; i < 8; i++) s += sw_[i];
        atomicAdd(out, s * __ldcg(&g_scale));    // * WEIGHT (=1.0); out zeroed by k_mm
    }
}

extern "C" void kernel_launch(void* const* d_in, const int* in_sizes, int n_in,
                              void* d_out, int out_size)
{
    const float* input = (const float*)d_in[0];
    const float* match = (const float*)d_in[1];
    const float* mask  = (const float*)d_in[2];

    k_mm<<<GRID_M, 256>>>(input, match, mask, (float*)d_out);

    cudaLaunchAttribute attr[1];
    attr[0].id = cudaLaunchAttributeProgrammaticStreamSerialization;
    attr[0].val.programmaticStreamSerializationAllowed = 1;

    cudaLaunchConfig_t cfg = {};
    cfg.blockDim = dim3(256, 1, 1);
    cfg.stream = 0;
    cfg.attrs = attr;
    cfg.numAttrs = 1;

    cfg.gridDim = dim3(GRID_M, 1, 1);
    cudaLaunchKernelEx(&cfg, k_hist, match, mask);

    cfg.gridDim = dim3(GRID_L, 1, 1);
    cudaLaunchKernelEx(&cfg, k_loss, input, mask, (float*)d_out);
}